// round 3
// baseline (speedup 1.0000x reference)
#include <cuda_runtime.h>

#define S_DIM 2048
#define B_DIM 32
#define E_DIM 1024
#define H_DIM 1024

#define BPB 16                       // blocks per batch element
#define ROWS_PER_BLOCK (S_DIM / BPB) // 128
#define WARPS 8
#define THREADS 256
#define ROWS_PER_WARP (ROWS_PER_BLOCK / WARPS) // 16

// Scratch (static __device__ — no allocations allowed)
__device__ float g_v[E_DIM];                       // W_enc^T w_score
__device__ float g_u[H_DIM];                       // W_dec^T w_score
__device__ float g_c[B_DIM];                       // h_t[b] . u
__device__ float g_wexp[B_DIM * S_DIM];            // exp(tanh(score)) per (b,s)
__device__ float g_partial[B_DIM * BPB * E_DIM];   // per-block weighted sums
__device__ float g_partial_l[B_DIM * BPB];         // per-block exp sums
__device__ float g_L[B_DIM];                       // softmax denominators

// ---------------------------------------------------------------------------
// K1: v[e] = sum_h ws[h]*W_enc[h,e];  u[h] = sum_g ws[g]*W_dec[g,h]
// ---------------------------------------------------------------------------
__global__ void k_proj(const float* __restrict__ W_enc,
                       const float* __restrict__ W_dec,
                       const float* __restrict__ w_score) {
    __shared__ float ws[H_DIM];
    int tid = threadIdx.x;
    for (int i = tid; i < H_DIM; i += THREADS) ws[i] = w_score[i];
    __syncthreads();

    if (blockIdx.x < 4) {
        int e = blockIdx.x * THREADS + tid;
        float acc = 0.f;
        #pragma unroll 8
        for (int h = 0; h < H_DIM; ++h) acc += ws[h] * W_enc[h * E_DIM + e];
        g_v[e] = acc;
    } else {
        int h = (blockIdx.x - 4) * THREADS + tid;
        float acc = 0.f;
        #pragma unroll 8
        for (int g = 0; g < H_DIM; ++g) acc += ws[g] * W_dec[g * H_DIM + h];
        g_u[h] = acc;
    }
}

// ---------------------------------------------------------------------------
// K2: c[b] = h_t[b] . u   (one warp per b, 32 warps in one block)
// ---------------------------------------------------------------------------
__global__ void k_c(const float* __restrict__ h_t) {
    int w = threadIdx.x >> 5;
    int lane = threadIdx.x & 31;
    const float* row = h_t + (size_t)w * H_DIM;
    float acc = 0.f;
    #pragma unroll
    for (int j = 0; j < H_DIM / 32; ++j)
        acc += row[lane + 32 * j] * g_u[lane + 32 * j];
    #pragma unroll
    for (int o = 16; o; o >>= 1) acc += __shfl_xor_sync(0xffffffffu, acc, o);
    if (lane == 0) g_c[w] = acc;
}

// ---------------------------------------------------------------------------
// K3: fused single pass over h_enc.
// One warp per row s: dot(he_row, v) -> tanh -> exp -> accumulate
// sum_exp and exp*he_row (register accumulator, 32 floats/lane).
// Block-combine 8 warps via smem slab, write per-block partials.
// ---------------------------------------------------------------------------
__global__ void k_main(const float* __restrict__ h_enc) {
    __shared__ float4 sv[E_DIM / 4];                 // 4 KB: v as float4
    __shared__ float4 slab[WARPS * (E_DIM / 4)];     // 32 KB
    __shared__ float  sl[WARPS];

    int tid  = threadIdx.x;
    int w    = tid >> 5;
    int lane = tid & 31;
    int b    = blockIdx.x / BPB;
    int blk  = blockIdx.x % BPB;

    sv[tid] = ((const float4*)g_v)[tid];
    __syncthreads();

    float cb = g_c[b];

    float4 acc[8];
    #pragma unroll
    for (int j = 0; j < 8; ++j) acc[j] = make_float4(0.f, 0.f, 0.f, 0.f);
    float lsum = 0.f;

    #pragma unroll 1
    for (int r = 0; r < ROWS_PER_WARP; ++r) {
        int s = blk * ROWS_PER_BLOCK + r * WARPS + w;
        const float4* row =
            (const float4*)(h_enc + ((size_t)s * B_DIM + b) * (size_t)E_DIM);

        float4 hv[8];
        float dot = 0.f;
        #pragma unroll
        for (int j = 0; j < 8; ++j) {
            hv[j] = row[lane + 32 * j];
            float4 vv = sv[lane + 32 * j];
            dot += hv[j].x * vv.x + hv[j].y * vv.y
                 + hv[j].z * vv.z + hv[j].w * vv.w;
        }
        #pragma unroll
        for (int o = 16; o; o >>= 1) dot += __shfl_xor_sync(0xffffffffu, dot, o);

        float sc  = tanhf(dot + cb);
        float wgt = __expf(sc);      // tanh in [-1,1] -> exp in [0.37,2.72]: safe
        if (lane == 0) g_wexp[b * S_DIM + s] = wgt;
        lsum += wgt;                 // uniform across warp

        #pragma unroll
        for (int j = 0; j < 8; ++j) {
            acc[j].x += wgt * hv[j].x;
            acc[j].y += wgt * hv[j].y;
            acc[j].z += wgt * hv[j].z;
            acc[j].w += wgt * hv[j].w;
        }
    }

    // block combine
    #pragma unroll
    for (int j = 0; j < 8; ++j) slab[w * (E_DIM / 4) + lane + 32 * j] = acc[j];
    if (lane == 0) sl[w] = lsum;
    __syncthreads();

    float4 sum = make_float4(0.f, 0.f, 0.f, 0.f);
    #pragma unroll
    for (int ww = 0; ww < WARPS; ++ww) {
        float4 v = slab[ww * (E_DIM / 4) + tid];
        sum.x += v.x; sum.y += v.y; sum.z += v.z; sum.w += v.w;
    }
    ((float4*)g_partial)[(size_t)(b * BPB + blk) * (E_DIM / 4) + tid] = sum;

    if (tid == 0) {
        float L = 0.f;
        #pragma unroll
        for (int ww = 0; ww < WARPS; ++ww) L += sl[ww];
        g_partial_l[b * BPB + blk] = L;
    }
}

// ---------------------------------------------------------------------------
// K4: combine BPB partials per batch, DIVIDE by L -> context (d_out[0:32768))
//     Also stash L[b] for the alphas kernel.
// ---------------------------------------------------------------------------
__global__ void k_combine(float* __restrict__ out_ctx) {
    __shared__ float sL;
    int b = blockIdx.x;
    int tid = threadIdx.x;

    if (tid == 0) {
        float L = 0.f;
        #pragma unroll
        for (int k = 0; k < BPB; ++k) L += g_partial_l[b * BPB + k];
        g_L[b] = L;
        sL = L;
    }
    __syncthreads();
    float invL = 1.0f / sL;

    const float4* p = (const float4*)g_partial + (size_t)b * BPB * (E_DIM / 4);
    float4 s = make_float4(0.f, 0.f, 0.f, 0.f);
    #pragma unroll
    for (int k = 0; k < BPB; ++k) {
        float4 v = p[(size_t)k * (E_DIM / 4) + tid];
        s.x += v.x; s.y += v.y; s.z += v.z; s.w += v.w;
    }
    s.x *= invL; s.y *= invL; s.z *= invL; s.w *= invL;
    ((float4*)out_ctx)[b * (E_DIM / 4) + tid] = s;
}

// ---------------------------------------------------------------------------
// K5: alphas[b,s] = wexp[b,s] / L[b]  -> d_out[32768 : 98304)
// ---------------------------------------------------------------------------
__global__ void k_alphas(float* __restrict__ out_alphas) {
    int idx = blockIdx.x * blockDim.x + threadIdx.x;
    int b = idx >> 11; // / S_DIM
    out_alphas[idx] = g_wexp[idx] / g_L[b];
}

// ---------------------------------------------------------------------------
extern "C" void kernel_launch(void* const* d_in, const int* in_sizes, int n_in,
                              void* d_out, int out_size) {
    const float* h_t     = (const float*)d_in[0];
    const float* h_enc   = (const float*)d_in[1];
    const float* W_enc   = (const float*)d_in[2];
    const float* W_dec   = (const float*)d_in[3];
    const float* w_score = (const float*)d_in[4];
    float* out = (float*)d_out;

    k_proj<<<8, THREADS>>>(W_enc, W_dec, w_score);
    k_c<<<1, 1024>>>(h_t);
    k_main<<<B_DIM * BPB, THREADS>>>(h_enc);
    k_combine<<<B_DIM, THREADS>>>(out);                    // context: out[0..32768)
    k_alphas<<<(B_DIM * S_DIM) / THREADS, THREADS>>>(out + B_DIM * E_DIM);
}

// round 5
// speedup vs baseline: 1.8535x; 1.8535x over previous
#include <cuda_runtime.h>

#define S_DIM 2048
#define B_DIM 32
#define E_DIM 1024
#define H_DIM 1024

#define BPB 16                       // blocks per batch element in k_main
#define ROWS_PER_BLOCK (S_DIM / BPB) // 128
#define WARPS 8
#define THREADS 256
#define ROWS_PER_WARP (ROWS_PER_BLOCK / WARPS) // 16

#define HP 16                        // h-chunks for split-K projection
#define HCHUNK (H_DIM / HP)          // 64

// Scratch (static __device__ — no allocations allowed)
__device__ float g_vpart[HP * E_DIM];
__device__ float g_upart[HP * H_DIM];
__device__ float g_v[E_DIM];
__device__ float g_u[H_DIM];
__device__ float g_c[B_DIM];
__device__ float g_wexp[B_DIM * S_DIM];
__device__ float g_ctx[B_DIM * E_DIM];       // atomic accumulation target
__device__ float g_partial_l[B_DIM * BPB];
__device__ float g_L[B_DIM];

// ---------------------------------------------------------------------------
// K1: split-K projections.
// Blocks 0..63:    v partials:  blk = ec*HP + hc  (ec in 0..3, hc in 0..15)
// Blocks 64..127:  u partials:  same decomposition for W_dec
// Each block: 256 e-columns x 64 h-rows.
// ---------------------------------------------------------------------------
__global__ void k_proj(const float* __restrict__ W_enc,
                       const float* __restrict__ W_dec,
                       const float* __restrict__ w_score) {
    __shared__ float ws[HCHUNK];
    int tid = threadIdx.x;
    bool is_v = blockIdx.x < 64;
    int blk = is_v ? blockIdx.x : blockIdx.x - 64;
    int ec = blk / HP;          // 0..3
    int hc = blk % HP;          // 0..15
    int e  = ec * THREADS + tid;
    int h0 = hc * HCHUNK;

    if (tid < HCHUNK) ws[tid] = w_score[h0 + tid];
    __syncthreads();

    const float* W = is_v ? W_enc : W_dec;
    float acc = 0.f;
    #pragma unroll 8
    for (int j = 0; j < HCHUNK; ++j)
        acc += ws[j] * W[(size_t)(h0 + j) * E_DIM + e];

    if (is_v) g_vpart[hc * E_DIM + e] = acc;
    else      g_upart[hc * H_DIM + e] = acc;
}

// ---------------------------------------------------------------------------
// K2 (merge): grid 2, block 1024.
// Block 0: reduce v partials; also zero g_ctx first half.
// Block 1: reduce u partials, then compute c[b] = h_t[b].u; zero g_ctx 2nd half.
// ---------------------------------------------------------------------------
__global__ void k_merge(const float* __restrict__ h_t) {
    int tid = threadIdx.x;
    if (blockIdx.x == 0) {
        float s = 0.f;
        #pragma unroll
        for (int k = 0; k < HP; ++k) s += g_vpart[k * E_DIM + tid];
        g_v[tid] = s;
        #pragma unroll
        for (int k = 0; k < 16; ++k) g_ctx[k * 1024 + tid] = 0.f;
    } else {
        float s = 0.f;
        #pragma unroll
        for (int k = 0; k < HP; ++k) s += g_upart[k * H_DIM + tid];
        g_u[tid] = s;
        #pragma unroll
        for (int k = 0; k < 16; ++k) g_ctx[(16 + k) * 1024 + tid] = 0.f;
        __syncthreads();
        // c[b]: one warp per b
        int w = tid >> 5, lane = tid & 31;
        const float* row = h_t + (size_t)w * H_DIM;
        float acc = 0.f;
        #pragma unroll
        for (int j = 0; j < H_DIM / 32; ++j)
            acc += row[lane + 32 * j] * g_u[lane + 32 * j];
        #pragma unroll
        for (int o = 16; o; o >>= 1) acc += __shfl_xor_sync(0xffffffffu, acc, o);
        if (lane == 0) g_c[w] = acc;
    }
}

// ---------------------------------------------------------------------------
// K3: fused single pass over h_enc, 2-row software pipeline per warp.
// ---------------------------------------------------------------------------
__global__ void __launch_bounds__(THREADS)
k_main(const float* __restrict__ h_enc) {
    __shared__ float4 sv[E_DIM / 4];                 // 4 KB
    __shared__ float4 slab[WARPS * (E_DIM / 4)];     // 32 KB
    __shared__ float  sl[WARPS];

    int tid  = threadIdx.x;
    int w    = tid >> 5;
    int lane = tid & 31;
    int b    = blockIdx.x / BPB;
    int blk  = blockIdx.x % BPB;

    sv[tid] = ((const float4*)g_v)[tid];
    __syncthreads();

    float cb = g_c[b];

    float4 acc[8];
    #pragma unroll
    for (int j = 0; j < 8; ++j) acc[j] = make_float4(0.f, 0.f, 0.f, 0.f);
    float lsum = 0.f;

    #pragma unroll 1
    for (int r = 0; r < ROWS_PER_WARP; r += 2) {
        int s0 = blk * ROWS_PER_BLOCK + r * WARPS + w;
        int s1 = s0 + WARPS;
        const float4* row0 =
            (const float4*)(h_enc + ((size_t)s0 * B_DIM + b) * (size_t)E_DIM);
        const float4* row1 =
            (const float4*)(h_enc + ((size_t)s1 * B_DIM + b) * (size_t)E_DIM);

        float4 hv0[8], hv1[8];
        // issue all 16 loads up front (max MLP)
        #pragma unroll
        for (int j = 0; j < 8; ++j) hv0[j] = row0[lane + 32 * j];
        #pragma unroll
        for (int j = 0; j < 8; ++j) hv1[j] = row1[lane + 32 * j];

        float dot0 = 0.f, dot1 = 0.f;
        #pragma unroll
        for (int j = 0; j < 8; ++j) {
            float4 vv = sv[lane + 32 * j];
            dot0 += hv0[j].x * vv.x + hv0[j].y * vv.y
                  + hv0[j].z * vv.z + hv0[j].w * vv.w;
            dot1 += hv1[j].x * vv.x + hv1[j].y * vv.y
                  + hv1[j].z * vv.z + hv1[j].w * vv.w;
        }
        #pragma unroll
        for (int o = 16; o; o >>= 1) {
            dot0 += __shfl_xor_sync(0xffffffffu, dot0, o);
            dot1 += __shfl_xor_sync(0xffffffffu, dot1, o);
        }

        float wgt0 = __expf(tanhf(dot0 + cb));   // tanh in [-1,1] -> exp safe
        float wgt1 = __expf(tanhf(dot1 + cb));
        if (lane == 0) {
            g_wexp[b * S_DIM + s0] = wgt0;
            g_wexp[b * S_DIM + s1] = wgt1;
        }
        lsum += wgt0 + wgt1;

        #pragma unroll
        for (int j = 0; j < 8; ++j) {
            acc[j].x += wgt0 * hv0[j].x + wgt1 * hv1[j].x;
            acc[j].y += wgt0 * hv0[j].y + wgt1 * hv1[j].y;
            acc[j].z += wgt0 * hv0[j].z + wgt1 * hv1[j].z;
            acc[j].w += wgt0 * hv0[j].w + wgt1 * hv1[j].w;
        }
    }

    // block combine
    #pragma unroll
    for (int j = 0; j < 8; ++j) slab[w * (E_DIM / 4) + lane + 32 * j] = acc[j];
    if (lane == 0) sl[w] = lsum;
    __syncthreads();

    float4 sum = make_float4(0.f, 0.f, 0.f, 0.f);
    #pragma unroll
    for (int ww = 0; ww < WARPS; ++ww) {
        float4 v = slab[ww * (E_DIM / 4) + tid];
        sum.x += v.x; sum.y += v.y; sum.z += v.z; sum.w += v.w;
    }
    // atomic accumulate into per-batch context numerator (spread addresses)
    float* dst = g_ctx + (size_t)b * E_DIM + 4 * tid;
    atomicAdd(dst + 0, sum.x);
    atomicAdd(dst + 1, sum.y);
    atomicAdd(dst + 2, sum.z);
    atomicAdd(dst + 3, sum.w);

    if (tid == 0) {
        float L = 0.f;
        #pragma unroll
        for (int ww = 0; ww < WARPS; ++ww) L += sl[ww];
        g_partial_l[b * BPB + blk] = L;
    }
}

// ---------------------------------------------------------------------------
// K4: finish — compute L[b], write context = g_ctx/L to d_out[0:32768)
// ---------------------------------------------------------------------------
__global__ void k_finish(float* __restrict__ out_ctx) {
    __shared__ float sL;
    int b = blockIdx.x;
    int tid = threadIdx.x;

    if (tid == 0) {
        float L = 0.f;
        #pragma unroll
        for (int k = 0; k < BPB; ++k) L += g_partial_l[b * BPB + k];
        g_L[b] = L;
        sL = L;
    }
    __syncthreads();
    float invL = 1.0f / sL;

    float4 v = ((const float4*)g_ctx)[b * (E_DIM / 4) + tid];
    v.x *= invL; v.y *= invL; v.z *= invL; v.w *= invL;
    ((float4*)out_ctx)[b * (E_DIM / 4) + tid] = v;
}

// ---------------------------------------------------------------------------
// K5: alphas[b,s] = wexp[b,s] / L[b]  -> d_out[32768 : 98304)
// ---------------------------------------------------------------------------
__global__ void k_alphas(float* __restrict__ out_alphas) {
    int idx = blockIdx.x * blockDim.x + threadIdx.x;
    int b = idx >> 11; // / S_DIM
    out_alphas[idx] = g_wexp[idx] / g_L[b];
}

// ---------------------------------------------------------------------------
extern "C" void kernel_launch(void* const* d_in, const int* in_sizes, int n_in,
                              void* d_out, int out_size) {
    const float* h_t     = (const float*)d_in[0];
    const float* h_enc   = (const float*)d_in[1];
    const float* W_enc   = (const float*)d_in[2];
    const float* W_dec   = (const float*)d_in[3];
    const float* w_score = (const float*)d_in[4];
    float* out = (float*)d_out;

    k_proj<<<128, THREADS>>>(W_enc, W_dec, w_score);
    k_merge<<<2, 1024>>>(h_t);
    k_main<<<B_DIM * BPB, THREADS>>>(h_enc);
    k_finish<<<B_DIM, THREADS>>>(out);
    k_alphas<<<(B_DIM * S_DIM) / THREADS, THREADS>>>(out + B_DIM * E_DIM);
}

// round 13
// speedup vs baseline: 2.4928x; 1.3449x over previous
#include <cuda_runtime.h>

#define S_DIM 2048
#define B_DIM 32
#define E_DIM 1024
#define H_DIM 1024

#define BPB 16                       // blocks per batch element in k_main
#define ROWS_PER_BLOCK (S_DIM / BPB) // 128
#define WARPS 8
#define THREADS 256
#define ROWS_PER_WARP (ROWS_PER_BLOCK / WARPS) // 16

#define HP 32                        // h-chunks for split-K projection
#define HCHUNK (H_DIM / HP)          // 32

// Scratch (static __device__ — no allocations allowed)
__device__ float g_vpart[HP * E_DIM];
__device__ float g_upart[HP * H_DIM];
__device__ float g_v[E_DIM];
__device__ float g_u[H_DIM];
__device__ float g_c[B_DIM];
__device__ float g_wexp[B_DIM * S_DIM];
__device__ float g_ctx[B_DIM * E_DIM];       // atomic accumulation target
__device__ float g_partial_l[B_DIM * BPB];

// ---------------------------------------------------------------------------
// K1: split-K projections.
// Blocks 0..127:   v partials:  blk = ec*HP + hc  (ec in 0..3, hc in 0..31)
// Blocks 128..255: u partials:  same decomposition for W_dec
// Each block: 256 e-columns x 32 h-rows.
// ---------------------------------------------------------------------------
__global__ void k_proj(const float* __restrict__ W_enc,
                       const float* __restrict__ W_dec,
                       const float* __restrict__ w_score) {
    __shared__ float ws[HCHUNK];
    int tid = threadIdx.x;
    bool is_v = blockIdx.x < 4 * HP;
    int blk = is_v ? blockIdx.x : blockIdx.x - 4 * HP;
    int ec = blk / HP;
    int hc = blk % HP;
    int e  = ec * THREADS + tid;
    int h0 = hc * HCHUNK;

    if (tid < HCHUNK) ws[tid] = w_score[h0 + tid];
    __syncthreads();

    const float* W = is_v ? W_enc : W_dec;
    float acc = 0.f;
    #pragma unroll
    for (int j = 0; j < HCHUNK; ++j)
        acc += ws[j] * W[(size_t)(h0 + j) * E_DIM + e];

    if (is_v) g_vpart[hc * E_DIM + e] = acc;
    else      g_upart[hc * H_DIM + e] = acc;
}

// ---------------------------------------------------------------------------
// K2 (merge): grid 2, block 1024.
// Block 0: reduce v partials; zero g_ctx first half.
// Block 1: reduce u partials, compute c[b] = h_t[b].u; zero g_ctx 2nd half.
// ---------------------------------------------------------------------------
__global__ void k_merge(const float* __restrict__ h_t) {
    int tid = threadIdx.x;
    if (blockIdx.x == 0) {
        float s = 0.f;
        #pragma unroll
        for (int k = 0; k < HP; ++k) s += g_vpart[k * E_DIM + tid];
        g_v[tid] = s;
        #pragma unroll
        for (int k = 0; k < 16; ++k) g_ctx[k * 1024 + tid] = 0.f;
    } else {
        float s = 0.f;
        #pragma unroll
        for (int k = 0; k < HP; ++k) s += g_upart[k * H_DIM + tid];
        g_u[tid] = s;
        #pragma unroll
        for (int k = 0; k < 16; ++k) g_ctx[(16 + k) * 1024 + tid] = 0.f;
        __syncthreads();
        // c[b]: one warp per b
        int w = tid >> 5, lane = tid & 31;
        const float* row = h_t + (size_t)w * H_DIM;
        float acc = 0.f;
        #pragma unroll
        for (int j = 0; j < H_DIM / 32; ++j)
            acc += row[lane + 32 * j] * g_u[lane + 32 * j];
        #pragma unroll
        for (int o = 16; o; o >>= 1) acc += __shfl_xor_sync(0xffffffffu, acc, o);
        if (lane == 0) g_c[w] = acc;
    }
}

// ---------------------------------------------------------------------------
// K3: fused single pass over h_enc, 2-row software pipeline per warp.
// Streaming loads (__ldcs): h_enc has zero reuse.
// ---------------------------------------------------------------------------
__global__ void __launch_bounds__(THREADS)
k_main(const float* __restrict__ h_enc) {
    __shared__ float4 sv[E_DIM / 4];                 // 4 KB
    __shared__ float4 slab[WARPS * (E_DIM / 4)];     // 32 KB
    __shared__ float  sl[WARPS];

    int tid  = threadIdx.x;
    int w    = tid >> 5;
    int lane = tid & 31;
    int b    = blockIdx.x / BPB;
    int blk  = blockIdx.x % BPB;

    sv[tid] = ((const float4*)g_v)[tid];
    __syncthreads();

    float cb = g_c[b];

    float4 acc[8];
    #pragma unroll
    for (int j = 0; j < 8; ++j) acc[j] = make_float4(0.f, 0.f, 0.f, 0.f);
    float lsum = 0.f;

    #pragma unroll 1
    for (int r = 0; r < ROWS_PER_WARP; r += 2) {
        int s0 = blk * ROWS_PER_BLOCK + r * WARPS + w;
        int s1 = s0 + WARPS;
        const float4* row0 =
            (const float4*)(h_enc + ((size_t)s0 * B_DIM + b) * (size_t)E_DIM);
        const float4* row1 =
            (const float4*)(h_enc + ((size_t)s1 * B_DIM + b) * (size_t)E_DIM);

        float4 hv0[8], hv1[8];
        // issue all 16 loads up front (max MLP), streaming
        #pragma unroll
        for (int j = 0; j < 8; ++j) hv0[j] = __ldcs(&row0[lane + 32 * j]);
        #pragma unroll
        for (int j = 0; j < 8; ++j) hv1[j] = __ldcs(&row1[lane + 32 * j]);

        float dot0 = 0.f, dot1 = 0.f;
        #pragma unroll
        for (int j = 0; j < 8; ++j) {
            float4 vv = sv[lane + 32 * j];
            dot0 += hv0[j].x * vv.x + hv0[j].y * vv.y
                  + hv0[j].z * vv.z + hv0[j].w * vv.w;
            dot1 += hv1[j].x * vv.x + hv1[j].y * vv.y
                  + hv1[j].z * vv.z + hv1[j].w * vv.w;
        }
        #pragma unroll
        for (int o = 16; o; o >>= 1) {
            dot0 += __shfl_xor_sync(0xffffffffu, dot0, o);
            dot1 += __shfl_xor_sync(0xffffffffu, dot1, o);
        }

        float wgt0 = __expf(tanhf(dot0 + cb));   // tanh in [-1,1] -> exp safe
        float wgt1 = __expf(tanhf(dot1 + cb));
        if (lane == 0) {
            g_wexp[b * S_DIM + s0] = wgt0;
            g_wexp[b * S_DIM + s1] = wgt1;
        }
        lsum += wgt0 + wgt1;

        #pragma unroll
        for (int j = 0; j < 8; ++j) {
            acc[j].x += wgt0 * hv0[j].x + wgt1 * hv1[j].x;
            acc[j].y += wgt0 * hv0[j].y + wgt1 * hv1[j].y;
            acc[j].z += wgt0 * hv0[j].z + wgt1 * hv1[j].z;
            acc[j].w += wgt0 * hv0[j].w + wgt1 * hv1[j].w;
        }
    }

    // block combine
    #pragma unroll
    for (int j = 0; j < 8; ++j) slab[w * (E_DIM / 4) + lane + 32 * j] = acc[j];
    if (lane == 0) sl[w] = lsum;
    __syncthreads();

    float4 sum = make_float4(0.f, 0.f, 0.f, 0.f);
    #pragma unroll
    for (int ww = 0; ww < WARPS; ++ww) {
        float4 v = slab[ww * (E_DIM / 4) + tid];
        sum.x += v.x; sum.y += v.y; sum.z += v.z; sum.w += v.w;
    }
    // atomic accumulate into per-batch context numerator (spread addresses)
    float* dst = g_ctx + (size_t)b * E_DIM + 4 * tid;
    atomicAdd(dst + 0, sum.x);
    atomicAdd(dst + 1, sum.y);
    atomicAdd(dst + 2, sum.z);
    atomicAdd(dst + 3, sum.w);

    if (tid == 0) {
        float L = 0.f;
        #pragma unroll
        for (int ww = 0; ww < WARPS; ++ww) L += sl[ww];
        g_partial_l[b * BPB + blk] = L;
    }
}

// ---------------------------------------------------------------------------
// K4 (tail): single kernel for context + alphas.
// Blocks 0..31:   context[b] = g_ctx[b]/L[b]       -> d_out[0 : 32768)
// Blocks 32..287: alphas = wexp/L[b]               -> d_out[32768 : 98304)
// Each block recomputes its own L[b] from g_partial_l (16 floats, L2-hot) —
// no cross-block dependency.
// ---------------------------------------------------------------------------
__global__ void k_tail(float* __restrict__ out) {
    int tid = threadIdx.x;
    if (blockIdx.x < B_DIM) {
        int b = blockIdx.x;
        float L = 0.f;
        #pragma unroll
        for (int k = 0; k < BPB; ++k) L += g_partial_l[b * BPB + k];
        float invL = 1.0f / L;
        float4 v = ((const float4*)g_ctx)[b * (E_DIM / 4) + tid];
        v.x *= invL; v.y *= invL; v.z *= invL; v.w *= invL;
        ((float4*)out)[b * (E_DIM / 4) + tid] = v;
    } else {
        int idx = (blockIdx.x - B_DIM) * THREADS + tid;  // 0 .. 65535
        int b = idx >> 11;
        float L = 0.f;
        #pragma unroll
        for (int k = 0; k < BPB; ++k) L += g_partial_l[b * BPB + k];
        out[B_DIM * E_DIM + idx] = g_wexp[idx] / L;
    }
}

// ---------------------------------------------------------------------------
extern "C" void kernel_launch(void* const* d_in, const int* in_sizes, int n_in,
                              void* d_out, int out_size) {
    const float* h_t     = (const float*)d_in[0];
    const float* h_enc   = (const float*)d_in[1];
    const float* W_enc   = (const float*)d_in[2];
    const float* W_dec   = (const float*)d_in[3];
    const float* w_score = (const float*)d_in[4];
    float* out = (float*)d_out;

    k_proj<<<8 * HP, THREADS>>>(W_enc, W_dec, w_score);
    k_merge<<<2, 1024>>>(h_t);
    k_main<<<B_DIM * BPB, THREADS>>>(h_enc);
    k_tail<<<B_DIM + (B_DIM * S_DIM) / THREADS, THREADS>>>(out);
}